// round 7
// baseline (speedup 1.0000x reference)
#include <cuda_runtime.h>
#include <cuda_bf16.h>
#include <cstdint>

// ---------------------------------------------------------------------------
// miScore: out[i,k] = (1/256) * sum_j sigmoid( y_a[i,:] . (W @ y_b[j,:] + b) )
//
// S0: convert y_a -> fp8(e4m3), y_b/W -> bf16 (one kernel)
// S1: proj = y_b @ W^T + b   (HMMA bf16, fp32 acc, fp8 store)
// S2: fused FP8 MMA GEMM (y_a @ proj^T) + tanh-sigmoid + row partials
//     CTA 128x128, 4 warps (warp tile 64x64), K=256 in 4 BK=64(fp8) chunks,
//     double-buffered cp.async, 2 CTAs/SM.
// S3: reduce 64 partials + broadcast
// ---------------------------------------------------------------------------

#define NUSR 8192
#define HDIM 256

__device__ __align__(16) uint8_t g_ya8[NUSR * HDIM];          // 2 MB  fp8
__device__ __align__(16) __nv_bfloat16 g_yb[NUSR * HDIM];     // 4 MB
__device__ __align__(16) __nv_bfloat16 g_wb[HDIM * HDIM];     // 128 KB
__device__ __align__(16) uint8_t g_proj8[NUSR * HDIM];        // 2 MB  fp8
__device__ float g_part[64][NUSR];                            // 2 MB
__device__ float g_s[NUSR];

// ---------------- cp.async helpers ----------------
__device__ __forceinline__ void cp_async16(uint32_t dst, const void* src) {
    asm volatile("cp.async.cg.shared.global [%0], [%1], 16;" :: "r"(dst), "l"(src));
}
#define CP_COMMIT() asm volatile("cp.async.commit_group;" ::: "memory")
#define CP_WAIT1()  asm volatile("cp.async.wait_group 1;" ::: "memory")
#define CP_WAIT0()  asm volatile("cp.async.wait_group 0;" ::: "memory")

// ---------------- mma / ldmatrix ----------------
__device__ __forceinline__ void ldsm_x4(uint32_t* r, uint32_t addr) {
    asm volatile("ldmatrix.sync.aligned.m8n8.x4.shared.b16 {%0,%1,%2,%3}, [%4];"
                 : "=r"(r[0]), "=r"(r[1]), "=r"(r[2]), "=r"(r[3]) : "r"(addr));
}
__device__ __forceinline__ void mma16816(float* c, const uint32_t* a, const uint32_t* b) {
    asm volatile(
        "mma.sync.aligned.m16n8k16.row.col.f32.bf16.bf16.f32 "
        "{%0,%1,%2,%3}, {%4,%5,%6,%7}, {%8,%9}, {%0,%1,%2,%3};"
        : "+f"(c[0]), "+f"(c[1]), "+f"(c[2]), "+f"(c[3])
        : "r"(a[0]), "r"(a[1]), "r"(a[2]), "r"(a[3]), "r"(b[0]), "r"(b[1]));
}
__device__ __forceinline__ void mma16832_fp8(float* c, const uint32_t* a, const uint32_t* b) {
    asm volatile(
        "mma.sync.aligned.m16n8k32.row.col.f32.e4m3.e4m3.f32 "
        "{%0,%1,%2,%3}, {%4,%5,%6,%7}, {%8,%9}, {%0,%1,%2,%3};"
        : "+f"(c[0]), "+f"(c[1]), "+f"(c[2]), "+f"(c[3])
        : "r"(a[0]), "r"(a[1]), "r"(a[2]), "r"(a[3]), "r"(b[0]), "r"(b[1]));
}
__device__ __forceinline__ float fast_tanh(float x) {
    float t;
    asm("tanh.approx.f32 %0, %1;" : "=f"(t) : "f"(x));
    return t;
}
// pack two floats -> e4m3x2 (lo = first arg in memory order)
__device__ __forceinline__ uint16_t pack_e4m3x2(float lo, float hi) {
    uint16_t r;
    asm("cvt.rn.satfinite.e4m3x2.f32 %0, %1, %2;" : "=h"(r) : "f"(hi), "f"(lo));
    return r;
}

// ===========================================================================
// S0: convert. y_a -> fp8, y_b/W -> bf16. One float4 per thread.
// ===========================================================================
__global__ void convert_all_kernel(const float* __restrict__ ya,
                                   const float* __restrict__ yb,
                                   const float* __restrict__ W) {
    const int idx = blockIdx.x * 256 + threadIdx.x;
    if (idx < 524288) {
        float4 v = ((const float4*)ya)[idx];
        uint32_t p = (uint32_t)pack_e4m3x2(v.x, v.y) |
                     ((uint32_t)pack_e4m3x2(v.z, v.w) << 16);
        ((uint32_t*)g_ya8)[idx] = p;
    } else if (idx < 1048576) {
        const int off = idx - 524288;
        float4 v = ((const float4*)yb)[off];
        __nv_bfloat162* dst = (__nv_bfloat162*)g_yb;
        dst[off * 2 + 0] = __floats2bfloat162_rn(v.x, v.y);
        dst[off * 2 + 1] = __floats2bfloat162_rn(v.z, v.w);
    } else {
        const int off = idx - 1048576;
        float4 v = ((const float4*)W)[off];
        __nv_bfloat162* dst = (__nv_bfloat162*)g_wb;
        dst[off * 2 + 0] = __floats2bfloat162_rn(v.x, v.y);
        dst[off * 2 + 1] = __floats2bfloat162_rn(v.z, v.w);
    }
}

// ===========================================================================
// S1: proj = y_b @ W^T + b (HMMA bf16). CTA 128(Mj) x 128(Ns); grid (2, 64).
//     Epilogue stores fp8.
// ===========================================================================
#define PSROW 40
#define PA_BYTES (128 * PSROW * 2)
#define PBUF_BYTES (2 * PA_BYTES)

__global__ void __launch_bounds__(256, 1) proj_hmma_kernel(const float* __restrict__ bias) {
    __shared__ __align__(16) char smem[2 * PBUF_BYTES];
    const uint32_t sbase = (uint32_t)__cvta_generic_to_shared(smem);

    const int tid = threadIdx.x;
    const int wid = tid >> 5, lane = tid & 31;
    const int wm0 = (wid & 1) * 64;
    const int wn0 = (wid >> 1) * 32;
    const int j0 = blockIdx.y * 128;
    const int s0 = blockIdx.x * 128;

    float acc[4][4][4];
    #pragma unroll
    for (int mt = 0; mt < 4; mt++)
        #pragma unroll
        for (int nt = 0; nt < 4; nt++)
            #pragma unroll
            for (int e = 0; e < 4; e++) acc[mt][nt][e] = 0.0f;

    auto load_chunk = [&](uint32_t dstb, int kt) {
        #pragma unroll
        for (int t = 0; t < 4; t++) {
            int g = tid + t * 256;
            if (g < 512) {
                int row = g >> 2, c = g & 3;
                cp_async16(dstb + (row * PSROW + c * 8) * 2,
                           g_yb + (size_t)(j0 + row) * HDIM + kt + c * 8);
            } else {
                int gb = g - 512;
                int row = gb >> 2, c = gb & 3;
                cp_async16(dstb + PA_BYTES + (row * PSROW + c * 8) * 2,
                           g_wb + (size_t)(s0 + row) * HDIM + kt + c * 8);
            }
        }
        CP_COMMIT();
    };

    load_chunk(sbase, 0);

    const int sub = lane >> 3, r8 = lane & 7;

    int buf = 0;
    #pragma unroll 1
    for (int it = 0; it < 8; it++) {
        if (it < 7) { load_chunk(sbase + (1 - buf) * PBUF_BYTES, (it + 1) * 32); CP_WAIT1(); }
        else        { CP_WAIT0(); }
        __syncthreads();

        const uint32_t aBase = sbase + buf * PBUF_BYTES;
        const uint32_t bBase = aBase + PA_BYTES;

        #pragma unroll
        for (int kk = 0; kk < 32; kk += 16) {
            uint32_t afrag[4][4];
            #pragma unroll
            for (int mt = 0; mt < 4; mt++) {
                int row = wm0 + mt * 16 + (sub & 1) * 8 + r8;
                int col = kk + (sub >> 1) * 8;
                ldsm_x4(afrag[mt], aBase + (row * PSROW + col) * 2);
            }
            uint32_t bfrag[4][2];
            #pragma unroll
            for (int p = 0; p < 2; p++) {
                int row = wn0 + p * 16 + (sub >> 1) * 8 + r8;
                int col = kk + (sub & 1) * 8;
                uint32_t t4[4];
                ldsm_x4(t4, bBase + (row * PSROW + col) * 2);
                bfrag[p * 2 + 0][0] = t4[0]; bfrag[p * 2 + 0][1] = t4[1];
                bfrag[p * 2 + 1][0] = t4[2]; bfrag[p * 2 + 1][1] = t4[3];
            }
            #pragma unroll
            for (int mt = 0; mt < 4; mt++)
                #pragma unroll
                for (int nt = 0; nt < 4; nt++)
                    mma16816(acc[mt][nt], afrag[mt], bfrag[nt]);
        }
        __syncthreads();
        buf ^= 1;
    }

    // epilogue: + bias, store fp8 (pairs are 2-byte aligned)
    #pragma unroll
    for (int nt = 0; nt < 4; nt++) {
        const int gc = s0 + wn0 + nt * 8 + 2 * (lane & 3);
        const float b0 = bias[gc], b1 = bias[gc + 1];
        #pragma unroll
        for (int mt = 0; mt < 4; mt++) {
            const int rlo = j0 + wm0 + mt * 16 + (lane >> 2);
            *((uint16_t*)&g_proj8[(size_t)rlo * HDIM + gc]) =
                pack_e4m3x2(acc[mt][nt][0] + b0, acc[mt][nt][1] + b1);
            *((uint16_t*)&g_proj8[(size_t)(rlo + 8) * HDIM + gc]) =
                pack_e4m3x2(acc[mt][nt][2] + b0, acc[mt][nt][3] + b1);
        }
    }
}

// ===========================================================================
// S2: fused FP8 MMA GEMM + tanh-sigmoid + row partials.
//   CTA 128(M=i) x 128(N=j); 4 warps as 2(M) x 2(N); warp tile 64x64.
//   K=256 fp8 in 4 chunks of 64 (64 B rows + 16 B pad = 80 B stride).
//   fp8 k32 fragments == bf16 k16 fragments in the b16 view -> same ldsm.
// ===========================================================================
#define SROW16 40                            // row stride in b16 units (80 B)
#define SA_BYTES (128 * SROW16 * 2)          // 10240
#define BUF_BYTES (2 * SA_BYTES)             // 20480 (A + B)
#define SROWS_OFF (2 * BUF_BYTES)            // 40960
#define FUSED_SMEM (SROWS_OFF + 2 * 128 * 4) // 41984

__global__ void __launch_bounds__(128, 2) fused_fp8_kernel() {
    extern __shared__ __align__(16) char smem[];
    const uint32_t sbase = (uint32_t)__cvta_generic_to_shared(smem);
    float* s_rows = (float*)(smem + SROWS_OFF);   // [2][128]

    const int tid = threadIdx.x;
    const int wid = tid >> 5, lane = tid & 31;
    const int wm0 = (wid & 1) * 64;
    const int wn0 = (wid >> 1) * 64;
    const int i0 = blockIdx.y * 128;
    const int j0 = blockIdx.x * 128;

    float acc[4][8][4];
    #pragma unroll
    for (int mt = 0; mt < 4; mt++)
        #pragma unroll
        for (int nt = 0; nt < 8; nt++)
            #pragma unroll
            for (int e = 0; e < 4; e++) acc[mt][nt][e] = 0.0f;

    // loader: A 512 + B 512 granules of 16 B; 8 per thread. 64 B per row.
    auto load_chunk = [&](uint32_t dstb, int kt) {
        #pragma unroll
        for (int t = 0; t < 8; t++) {
            int g = tid + t * 128;
            if (g < 512) {
                int row = g >> 2, c = g & 3;
                cp_async16(dstb + row * 80 + c * 16,
                           g_ya8 + (size_t)(i0 + row) * HDIM + kt + c * 16);
            } else {
                int gb = g - 512;
                int row = gb >> 2, c = gb & 3;
                cp_async16(dstb + SA_BYTES + row * 80 + c * 16,
                           g_proj8 + (size_t)(j0 + row) * HDIM + kt + c * 16);
            }
        }
        CP_COMMIT();
    };

    load_chunk(sbase, 0);

    const int sub = lane >> 3, r8 = lane & 7;

    int buf = 0;
    #pragma unroll 1
    for (int it = 0; it < 4; it++) {
        if (it < 3) { load_chunk(sbase + (1 - buf) * BUF_BYTES, (it + 1) * 64); CP_WAIT1(); }
        else        { CP_WAIT0(); }
        __syncthreads();

        const uint32_t aBase = sbase + buf * BUF_BYTES;
        const uint32_t bBase = aBase + SA_BYTES;

        // 2 k32 slices per chunk; slice s covers b16 cols [s*16, s*16+16)
        #pragma unroll
        for (int s = 0; s < 2; s++) {
            const int colA = s * 16 + (sub >> 1) * 8;   // b16 units
            const int colB = s * 16 + (sub & 1) * 8;
            uint32_t afrag[4][4];
            #pragma unroll
            for (int mt = 0; mt < 4; mt++) {
                int row = wm0 + mt * 16 + (sub & 1) * 8 + r8;
                ldsm_x4(afrag[mt], aBase + (row * SROW16 + colA) * 2);
            }
            uint32_t bfrag[8][2];
            #pragma unroll
            for (int p = 0; p < 4; p++) {
                int row = wn0 + p * 16 + (sub >> 1) * 8 + r8;
                uint32_t t4[4];
                ldsm_x4(t4, bBase + (row * SROW16 + colB) * 2);
                bfrag[p * 2 + 0][0] = t4[0]; bfrag[p * 2 + 0][1] = t4[1];
                bfrag[p * 2 + 1][0] = t4[2]; bfrag[p * 2 + 1][1] = t4[3];
            }
            #pragma unroll
            for (int mt = 0; mt < 4; mt++)
                #pragma unroll
                for (int nt = 0; nt < 8; nt++)
                    mma16832_fp8(acc[mt][nt], afrag[mt], bfrag[nt]);
        }
        __syncthreads();
        buf ^= 1;
    }

    // epilogue: sigmoid(x) = 0.5*tanh(x/2) + 0.5
    float rs[4][2];
    #pragma unroll
    for (int mt = 0; mt < 4; mt++) { rs[mt][0] = 0.0f; rs[mt][1] = 0.0f; }
    #pragma unroll
    for (int mt = 0; mt < 4; mt++)
        #pragma unroll
        for (int nt = 0; nt < 8; nt++) {
            rs[mt][0] += 0.5f * fast_tanh(0.5f * acc[mt][nt][0])
                       + 0.5f * fast_tanh(0.5f * acc[mt][nt][1]);
            rs[mt][1] += 0.5f * fast_tanh(0.5f * acc[mt][nt][2])
                       + 0.5f * fast_tanh(0.5f * acc[mt][nt][3]);
        }
    #pragma unroll
    for (int mt = 0; mt < 4; mt++)
        #pragma unroll
        for (int h = 0; h < 2; h++) {
            rs[mt][h] += __shfl_xor_sync(0xffffffffu, rs[mt][h], 1);
            rs[mt][h] += __shfl_xor_sync(0xffffffffu, rs[mt][h], 2);
        }
    if ((lane & 3) == 0) {
        const int rq = lane >> 2;
        const int wn = wid >> 1;
        #pragma unroll
        for (int mt = 0; mt < 4; mt++) {
            s_rows[wn * 128 + wm0 + mt * 16 + 0 + rq] = rs[mt][0] + 32.0f;
            s_rows[wn * 128 + wm0 + mt * 16 + 8 + rq] = rs[mt][1] + 32.0f;
        }
    }
    __syncthreads();
    g_part[blockIdx.x][i0 + tid] = s_rows[tid] + s_rows[128 + tid];
}

// ===========================================================================
// S3: reduce 64 partials + broadcast. One warp per output row.
// ===========================================================================
__global__ void reduce_bcast_kernel(float* __restrict__ out) {
    const int wid = threadIdx.x >> 5, lane = threadIdx.x & 31;
    const int row = blockIdx.x * 8 + wid;
    float s = g_part[lane][row] + g_part[lane + 32][row];
    #pragma unroll
    for (int d = 16; d > 0; d >>= 1) s += __shfl_xor_sync(0xffffffffu, s, d);
    const float v = s * (1.0f / 256.0f);
    float4* dst = (float4*)(out + (size_t)row * HDIM);
    const float4 vv = make_float4(v, v, v, v);
    dst[lane]      = vv;
    dst[lane + 32] = vv;
}

// ===========================================================================
extern "C" void kernel_launch(void* const* d_in, const int* in_sizes, int n_in,
                              void* d_out, int out_size) {
    const float* y_a = (const float*)d_in[0];
    const float* y_b = (const float*)d_in[1];
    const float* W   = (const float*)d_in[2];
    const float* b   = (const float*)d_in[3];
    float* out = (float*)d_out;

    convert_all_kernel<<<4160, 256>>>(y_a, y_b, W);
    proj_hmma_kernel<<<dim3(2, 64), 256>>>(b);
    fused_fp8_kernel<<<dim3(NUSR / 128, NUSR / 128), 128, FUSED_SMEM>>>();
    reduce_bcast_kernel<<<NUSR / 8, 256>>>(out);
}

// round 8
// speedup vs baseline: 1.0524x; 1.0524x over previous
#include <cuda_runtime.h>
#include <cuda_bf16.h>
#include <cstdint>

// ---------------------------------------------------------------------------
// miScore: out[i,k] = (1/256) * sum_j sigmoid( y_a[i,:] . (W @ y_b[j,:] + b) )
//
// S0: convert y_a, y_b, W fp32 -> bf16 (one kernel)
// S1: proj = y_b @ W^T + b   (HMMA bf16, bias epilogue, bf16 store)
// S2: PERSISTENT fused HMMA bf16 GEMM + tanh-sigmoid + row partials
//     304 CTAs (2/SM) x 128 thr; tile 128x128 (warp tile 64x64);
//     BK=32 chunks in a 5-stage cp.async ring (depth-3 prefetch),
//     one __syncthreads per chunk; pipeline runs across tiles.
// S3: reduce 64 partials + broadcast
// ---------------------------------------------------------------------------

#define NUSR 8192
#define HDIM 256
#define NTILE 4096          // 64 x 64 tiles of 128x128
#define PGRID 304           // 2 CTAs per SM on 152 SMs

__device__ __align__(16) __nv_bfloat16 g_ya[NUSR * HDIM];     // 4 MB
__device__ __align__(16) __nv_bfloat16 g_yb[NUSR * HDIM];     // 4 MB
__device__ __align__(16) __nv_bfloat16 g_wb[HDIM * HDIM];     // 128 KB
__device__ __align__(16) __nv_bfloat16 g_projb[NUSR * HDIM];  // 4 MB
__device__ float g_part[64][NUSR];                            // 2 MB
__device__ float g_s[NUSR];

// ---------------- cp.async helpers ----------------
__device__ __forceinline__ void cp_async16(uint32_t dst, const void* src) {
    asm volatile("cp.async.cg.shared.global [%0], [%1], 16;" :: "r"(dst), "l"(src));
}
#define CP_COMMIT() asm volatile("cp.async.commit_group;" ::: "memory")
#define CP_WAIT2()  asm volatile("cp.async.wait_group 2;" ::: "memory")
#define CP_WAIT1()  asm volatile("cp.async.wait_group 1;" ::: "memory")
#define CP_WAIT0()  asm volatile("cp.async.wait_group 0;" ::: "memory")

// ---------------- mma / ldmatrix ----------------
__device__ __forceinline__ void ldsm_x4(uint32_t* r, uint32_t addr) {
    asm volatile("ldmatrix.sync.aligned.m8n8.x4.shared.b16 {%0,%1,%2,%3}, [%4];"
                 : "=r"(r[0]), "=r"(r[1]), "=r"(r[2]), "=r"(r[3]) : "r"(addr));
}
__device__ __forceinline__ void mma16816(float* c, const uint32_t* a, const uint32_t* b) {
    asm volatile(
        "mma.sync.aligned.m16n8k16.row.col.f32.bf16.bf16.f32 "
        "{%0,%1,%2,%3}, {%4,%5,%6,%7}, {%8,%9}, {%0,%1,%2,%3};"
        : "+f"(c[0]), "+f"(c[1]), "+f"(c[2]), "+f"(c[3])
        : "r"(a[0]), "r"(a[1]), "r"(a[2]), "r"(a[3]), "r"(b[0]), "r"(b[1]));
}
__device__ __forceinline__ float fast_tanh(float x) {
    float t;
    asm("tanh.approx.f32 %0, %1;" : "=f"(t) : "f"(x));
    return t;
}

// ===========================================================================
// S0: convert y_a, y_b, W to bf16. One float4 per thread.
// ===========================================================================
__global__ void convert_all_kernel(const float* __restrict__ ya,
                                   const float* __restrict__ yb,
                                   const float* __restrict__ W) {
    const int idx = blockIdx.x * 256 + threadIdx.x;
    const float* src;
    __nv_bfloat162* dst;
    int off;
    if (idx < 524288) {
        src = ya; dst = (__nv_bfloat162*)g_ya; off = idx;
    } else if (idx < 1048576) {
        src = yb; dst = (__nv_bfloat162*)g_yb; off = idx - 524288;
    } else {
        src = W;  dst = (__nv_bfloat162*)g_wb; off = idx - 1048576;
    }
    float4 v = ((const float4*)src)[off];
    dst[off * 2 + 0] = __floats2bfloat162_rn(v.x, v.y);
    dst[off * 2 + 1] = __floats2bfloat162_rn(v.z, v.w);
}

// ===========================================================================
// S1: proj = y_b @ W^T + b (HMMA). CTA 128(Mj) x 128(Ns); grid (2, 64).
// ===========================================================================
#define PSROW 40
#define PA_BYTES (128 * PSROW * 2)
#define PBUF_BYTES (2 * PA_BYTES)

__global__ void __launch_bounds__(256, 1) proj_hmma_kernel(const float* __restrict__ bias) {
    __shared__ __align__(16) char smem[2 * PBUF_BYTES];
    const uint32_t sbase = (uint32_t)__cvta_generic_to_shared(smem);

    const int tid = threadIdx.x;
    const int wid = tid >> 5, lane = tid & 31;
    const int wm0 = (wid & 1) * 64;
    const int wn0 = (wid >> 1) * 32;
    const int j0 = blockIdx.y * 128;
    const int s0 = blockIdx.x * 128;

    float acc[4][4][4];
    #pragma unroll
    for (int mt = 0; mt < 4; mt++)
        #pragma unroll
        for (int nt = 0; nt < 4; nt++)
            #pragma unroll
            for (int e = 0; e < 4; e++) acc[mt][nt][e] = 0.0f;

    auto load_chunk = [&](uint32_t dstb, int kt) {
        #pragma unroll
        for (int t = 0; t < 4; t++) {
            int g = tid + t * 256;
            if (g < 512) {
                int row = g >> 2, c = g & 3;
                cp_async16(dstb + (row * PSROW + c * 8) * 2,
                           g_yb + (size_t)(j0 + row) * HDIM + kt + c * 8);
            } else {
                int gb = g - 512;
                int row = gb >> 2, c = gb & 3;
                cp_async16(dstb + PA_BYTES + (row * PSROW + c * 8) * 2,
                           g_wb + (size_t)(s0 + row) * HDIM + kt + c * 8);
            }
        }
        CP_COMMIT();
    };

    load_chunk(sbase, 0);

    const int sub = lane >> 3, r8 = lane & 7;

    int buf = 0;
    #pragma unroll 1
    for (int it = 0; it < 8; it++) {
        if (it < 7) { load_chunk(sbase + (1 - buf) * PBUF_BYTES, (it + 1) * 32); CP_WAIT1(); }
        else        { CP_WAIT0(); }
        __syncthreads();

        const uint32_t aBase = sbase + buf * PBUF_BYTES;
        const uint32_t bBase = aBase + PA_BYTES;

        #pragma unroll
        for (int kk = 0; kk < 32; kk += 16) {
            uint32_t afrag[4][4];
            #pragma unroll
            for (int mt = 0; mt < 4; mt++) {
                int row = wm0 + mt * 16 + (sub & 1) * 8 + r8;
                int col = kk + (sub >> 1) * 8;
                ldsm_x4(afrag[mt], aBase + (row * PSROW + col) * 2);
            }
            uint32_t bfrag[4][2];
            #pragma unroll
            for (int p = 0; p < 2; p++) {
                int row = wn0 + p * 16 + (sub >> 1) * 8 + r8;
                int col = kk + (sub & 1) * 8;
                uint32_t t4[4];
                ldsm_x4(t4, bBase + (row * PSROW + col) * 2);
                bfrag[p * 2 + 0][0] = t4[0]; bfrag[p * 2 + 0][1] = t4[1];
                bfrag[p * 2 + 1][0] = t4[2]; bfrag[p * 2 + 1][1] = t4[3];
            }
            #pragma unroll
            for (int mt = 0; mt < 4; mt++)
                #pragma unroll
                for (int nt = 0; nt < 4; nt++)
                    mma16816(acc[mt][nt], afrag[mt], bfrag[nt]);
        }
        __syncthreads();
        buf ^= 1;
    }

    #pragma unroll
    for (int nt = 0; nt < 4; nt++) {
        const int gc = s0 + wn0 + nt * 8 + 2 * (lane & 3);
        const float b0 = bias[gc], b1 = bias[gc + 1];
        #pragma unroll
        for (int mt = 0; mt < 4; mt++) {
            const int rlo = j0 + wm0 + mt * 16 + (lane >> 2);
            *((__nv_bfloat162*)&g_projb[(size_t)rlo * HDIM + gc]) =
                __floats2bfloat162_rn(acc[mt][nt][0] + b0, acc[mt][nt][1] + b1);
            *((__nv_bfloat162*)&g_projb[(size_t)(rlo + 8) * HDIM + gc]) =
                __floats2bfloat162_rn(acc[mt][nt][2] + b0, acc[mt][nt][3] + b1);
        }
    }
}

// ===========================================================================
// S2: persistent fused HMMA bf16 GEMM + sigmoid + row partials.
//   Tile 128x128, 4 warps 2(M)x2(N), warp tile 64x64.
//   Chunk = BK=32 (A 128x32 + B 128x32, 80 B row stride).
//   5-stage ring, prefetch depth 3, one sync per chunk, runs across tiles.
// ===========================================================================
#define SROW16 40                                   // 80 B row stride
#define CHA_BYTES (128 * SROW16 * 2)                // 10240 per matrix
#define CHBUF_BYTES (2 * CHA_BYTES)                 // 20480 per stage
#define NSTAGE 5
#define SROWS_OFF (NSTAGE * CHBUF_BYTES)            // 102400
#define FUSED_SMEM (SROWS_OFF + 2 * 128 * 4)        // 103424

__global__ void __launch_bounds__(128, 2) fused_hmma_persist() {
    extern __shared__ __align__(16) char smem[];
    const uint32_t sbase = (uint32_t)__cvta_generic_to_shared(smem);
    float* s_rows = (float*)(smem + SROWS_OFF);     // [2][128]

    const int tid = threadIdx.x;
    const int wid = tid >> 5, lane = tid & 31;
    const int wm0 = (wid & 1) * 64;
    const int wn0 = (wid >> 1) * 64;
    const int sub = lane >> 3, r8 = lane & 7;
    const int bid = blockIdx.x, gsz = gridDim.x;

    const int nt = (NTILE - bid + gsz - 1) / gsz;   // tiles for this CTA
    const int G = nt * 8;                           // chunks (8 per tile)

    // issue the loads for global chunk g into ring stage g%5
    auto load_chunk = [&](int g) {
        const int tile = bid + (g >> 3) * gsz;
        const int kt = (g & 7) * 32;                 // bf16 k offset
        const int i0 = (tile >> 6) * 128;
        const int j0 = (tile & 63) * 128;
        const uint32_t dstb = sbase + (g % NSTAGE) * CHBUF_BYTES;
        #pragma unroll
        for (int t = 0; t < 8; t++) {
            int gg = tid + t * 128;
            if (gg < 512) {                          // A: 128 rows x 64 B
                int row = gg >> 2, c = gg & 3;
                cp_async16(dstb + row * 80 + c * 16,
                           g_ya + (size_t)(i0 + row) * HDIM + kt + c * 8);
            } else {                                 // B
                int gb = gg - 512;
                int row = gb >> 2, c = gb & 3;
                cp_async16(dstb + CHA_BYTES + row * 80 + c * 16,
                           g_projb + (size_t)(j0 + row) * HDIM + kt + c * 8);
            }
        }
        CP_COMMIT();
    };

    float acc[4][8][4];
    #pragma unroll
    for (int mt = 0; mt < 4; mt++)
        #pragma unroll
        for (int nt2 = 0; nt2 < 8; nt2++)
            #pragma unroll
            for (int e = 0; e < 4; e++) acc[mt][nt2][e] = 0.0f;

    // prologue: prefetch 3 chunks
    load_chunk(0);
    if (G > 1) load_chunk(1);
    if (G > 2) load_chunk(2);

    #pragma unroll 1
    for (int g = 0; g < G; g++) {
        // wait until chunk g's group has completed
        const int ahead = G - 1 - g;
        if (ahead >= 2)      { CP_WAIT2(); }
        else if (ahead == 1) { CP_WAIT1(); }
        else                 { CP_WAIT0(); }
        __syncthreads();                             // data visible to all;
                                                     // also fences ring reuse
        if (g + 3 < G) load_chunk(g + 3);

        const uint32_t aBase = sbase + (g % NSTAGE) * CHBUF_BYTES;
        const uint32_t bBase = aBase + CHA_BYTES;

        #pragma unroll
        for (int kk = 0; kk < 32; kk += 16) {
            uint32_t afrag[4][4];
            #pragma unroll
            for (int mt = 0; mt < 4; mt++) {
                int row = wm0 + mt * 16 + (sub & 1) * 8 + r8;
                int col = kk + (sub >> 1) * 8;
                ldsm_x4(afrag[mt], aBase + (row * SROW16 + col) * 2);
            }
            uint32_t bfrag[8][2];
            #pragma unroll
            for (int p = 0; p < 4; p++) {
                int row = wn0 + p * 16 + (sub >> 1) * 8 + r8;
                int col = kk + (sub & 1) * 8;
                uint32_t t4[4];
                ldsm_x4(t4, bBase + (row * SROW16 + col) * 2);
                bfrag[p * 2 + 0][0] = t4[0]; bfrag[p * 2 + 0][1] = t4[1];
                bfrag[p * 2 + 1][0] = t4[2]; bfrag[p * 2 + 1][1] = t4[3];
            }
            #pragma unroll
            for (int mt = 0; mt < 4; mt++)
                #pragma unroll
                for (int nt2 = 0; nt2 < 8; nt2++)
                    mma16816(acc[mt][nt2], afrag[mt], bfrag[nt2]);
        }

        // ---- tile finished? epilogue ----
        if ((g & 7) == 7) {
            const int tile = bid + (g >> 3) * gsz;
            const int i0 = (tile >> 6) * 128;
            const int jb = tile & 63;

            float rs[4][2];
            #pragma unroll
            for (int mt = 0; mt < 4; mt++) { rs[mt][0] = 0.0f; rs[mt][1] = 0.0f; }
            #pragma unroll
            for (int mt = 0; mt < 4; mt++)
                #pragma unroll
                for (int nt2 = 0; nt2 < 8; nt2++) {
                    rs[mt][0] += 0.5f * fast_tanh(0.5f * acc[mt][nt2][0])
                               + 0.5f * fast_tanh(0.5f * acc[mt][nt2][1]);
                    rs[mt][1] += 0.5f * fast_tanh(0.5f * acc[mt][nt2][2])
                               + 0.5f * fast_tanh(0.5f * acc[mt][nt2][3]);
                }
            #pragma unroll
            for (int mt = 0; mt < 4; mt++)
                #pragma unroll
                for (int h = 0; h < 2; h++) {
                    rs[mt][h] += __shfl_xor_sync(0xffffffffu, rs[mt][h], 1);
                    rs[mt][h] += __shfl_xor_sync(0xffffffffu, rs[mt][h], 2);
                }
            if ((lane & 3) == 0) {
                const int rq = lane >> 2;
                const int wn = wid >> 1;
                #pragma unroll
                for (int mt = 0; mt < 4; mt++) {
                    s_rows[wn * 128 + wm0 + mt * 16 + 0 + rq] = rs[mt][0] + 32.0f;
                    s_rows[wn * 128 + wm0 + mt * 16 + 8 + rq] = rs[mt][1] + 32.0f;
                }
            }
            __syncthreads();
            g_part[jb][i0 + tid] = s_rows[tid] + s_rows[128 + tid];

            #pragma unroll
            for (int mt = 0; mt < 4; mt++)
                #pragma unroll
                for (int nt2 = 0; nt2 < 8; nt2++)
                    #pragma unroll
                    for (int e = 0; e < 4; e++) acc[mt][nt2][e] = 0.0f;
        }
    }
}

// ===========================================================================
// S3: reduce 64 partials + broadcast. One warp per output row.
// ===========================================================================
__global__ void reduce_bcast_kernel(float* __restrict__ out) {
    const int wid = threadIdx.x >> 5, lane = threadIdx.x & 31;
    const int row = blockIdx.x * 8 + wid;
    float s = g_part[lane][row] + g_part[lane + 32][row];
    #pragma unroll
    for (int d = 16; d > 0; d >>= 1) s += __shfl_xor_sync(0xffffffffu, s, d);
    const float v = s * (1.0f / 256.0f);
    float4* dst = (float4*)(out + (size_t)row * HDIM);
    const float4 vv = make_float4(v, v, v, v);
    dst[lane]      = vv;
    dst[lane + 32] = vv;
}

// ===========================================================================
extern "C" void kernel_launch(void* const* d_in, const int* in_sizes, int n_in,
                              void* d_out, int out_size) {
    const float* y_a = (const float*)d_in[0];
    const float* y_b = (const float*)d_in[1];
    const float* W   = (const float*)d_in[2];
    const float* b   = (const float*)d_in[3];
    float* out = (float*)d_out;

    cudaFuncSetAttribute(fused_hmma_persist,
                         cudaFuncAttributeMaxDynamicSharedMemorySize, FUSED_SMEM);

    convert_all_kernel<<<4160, 256>>>(y_a, y_b, W);
    proj_hmma_kernel<<<dim3(2, 64), 256>>>(b);
    fused_hmma_persist<<<PGRID, 128, FUSED_SMEM>>>();
    reduce_bcast_kernel<<<NUSR / 8, 256>>>(out);
}

// round 9
// speedup vs baseline: 1.1612x; 1.1034x over previous
#include <cuda_runtime.h>
#include <cuda_bf16.h>
#include <cstdint>

// ---------------------------------------------------------------------------
// miScore: out[i,k] = (1/256) * sum_j sigmoid( y_a[i,:] . (W @ y_b[j,:] + b) )
//
// S0: convert y_b, W fp32 -> bf16 (small kernel)
// S1: proj = y_b @ W^T + b (HMMA, 128 CTAs)  ||  convert y_a (128 CTAs)
//     -- one launch, independent block groups run concurrently
// S2: fused HMMA bf16 GEMM + tanh-sigmoid + row partials
//     CTA 128x128, 4 warps (64x64 warp tile), K=256 as 4 BK=64 chunks in a
//     3-stage cp.async ring -> ONE __syncthreads per chunk. 2 CTAs/SM.
// S3: reduce 64 partials + broadcast
// ---------------------------------------------------------------------------

#define NUSR 8192
#define HDIM 256

__device__ __align__(16) __nv_bfloat16 g_ya[NUSR * HDIM];     // 4 MB
__device__ __align__(16) __nv_bfloat16 g_yb[NUSR * HDIM];     // 4 MB
__device__ __align__(16) __nv_bfloat16 g_wb[HDIM * HDIM];     // 128 KB
__device__ __align__(16) __nv_bfloat16 g_projb[NUSR * HDIM];  // 4 MB
__device__ float g_part[64][NUSR];                            // 2 MB
__device__ float g_s[NUSR];

// ---------------- cp.async helpers ----------------
__device__ __forceinline__ void cp_async16(uint32_t dst, const void* src) {
    asm volatile("cp.async.cg.shared.global [%0], [%1], 16;" :: "r"(dst), "l"(src));
}
#define CP_COMMIT() asm volatile("cp.async.commit_group;" ::: "memory")
#define CP_WAIT1()  asm volatile("cp.async.wait_group 1;" ::: "memory")
#define CP_WAIT0()  asm volatile("cp.async.wait_group 0;" ::: "memory")

// ---------------- mma / ldmatrix ----------------
__device__ __forceinline__ void ldsm_x4(uint32_t* r, uint32_t addr) {
    asm volatile("ldmatrix.sync.aligned.m8n8.x4.shared.b16 {%0,%1,%2,%3}, [%4];"
                 : "=r"(r[0]), "=r"(r[1]), "=r"(r[2]), "=r"(r[3]) : "r"(addr));
}
__device__ __forceinline__ void mma16816(float* c, const uint32_t* a, const uint32_t* b) {
    asm volatile(
        "mma.sync.aligned.m16n8k16.row.col.f32.bf16.bf16.f32 "
        "{%0,%1,%2,%3}, {%4,%5,%6,%7}, {%8,%9}, {%0,%1,%2,%3};"
        : "+f"(c[0]), "+f"(c[1]), "+f"(c[2]), "+f"(c[3])
        : "r"(a[0]), "r"(a[1]), "r"(a[2]), "r"(a[3]), "r"(b[0]), "r"(b[1]));
}
__device__ __forceinline__ float fast_tanh(float x) {
    float t;
    asm("tanh.approx.f32 %0, %1;" : "=f"(t) : "f"(x));
    return t;
}

// ===========================================================================
// S0: convert y_b and W to bf16. 540672 float4 -> 2112 blocks x 256.
// ===========================================================================
__global__ void convert_ybw_kernel(const float* __restrict__ yb,
                                   const float* __restrict__ W) {
    const int idx = blockIdx.x * 256 + threadIdx.x;
    const float* src;
    __nv_bfloat162* dst;
    int off;
    if (idx < 524288) { src = yb; dst = (__nv_bfloat162*)g_yb; off = idx; }
    else              { src = W;  dst = (__nv_bfloat162*)g_wb; off = idx - 524288; }
    float4 v = ((const float4*)src)[off];
    dst[off * 2 + 0] = __floats2bfloat162_rn(v.x, v.y);
    dst[off * 2 + 1] = __floats2bfloat162_rn(v.z, v.w);
}

// ===========================================================================
// S1: blocks 0..127: proj = y_b @ W^T + b (HMMA, CTA 128x128)
//     blocks 128..255: convert y_a -> bf16 (16 float4 per thread)
// ===========================================================================
#define PSROW 40
#define PA_BYTES (128 * PSROW * 2)
#define PBUF_BYTES (2 * PA_BYTES)

__global__ void __launch_bounds__(256, 1) proj_and_convert_kernel(
        const float* __restrict__ bias, const float* __restrict__ ya) {
    __shared__ __align__(16) char smem[2 * PBUF_BYTES];

    const int tid = threadIdx.x;
    const int bx = blockIdx.x;

    if (bx >= 128) {   // ---- y_a conversion blocks ----
        const int base = (bx - 128) * 4096;
        __nv_bfloat162* dst = (__nv_bfloat162*)g_ya;
        #pragma unroll
        for (int u = 0; u < 16; u++) {
            const int off = base + u * 256 + tid;
            float4 v = ((const float4*)ya)[off];
            dst[off * 2 + 0] = __floats2bfloat162_rn(v.x, v.y);
            dst[off * 2 + 1] = __floats2bfloat162_rn(v.z, v.w);
        }
        return;
    }

    // ---- proj blocks ----
    const uint32_t sbase = (uint32_t)__cvta_generic_to_shared(smem);
    const int wid = tid >> 5, lane = tid & 31;
    const int wm0 = (wid & 1) * 64;
    const int wn0 = (wid >> 1) * 32;
    const int j0 = (bx >> 1) * 128;
    const int s0 = (bx & 1) * 128;

    float acc[4][4][4];
    #pragma unroll
    for (int mt = 0; mt < 4; mt++)
        #pragma unroll
        for (int nt = 0; nt < 4; nt++)
            #pragma unroll
            for (int e = 0; e < 4; e++) acc[mt][nt][e] = 0.0f;

    auto load_chunk = [&](uint32_t dstb, int kt) {
        #pragma unroll
        for (int t = 0; t < 4; t++) {
            int g = tid + t * 256;
            if (g < 512) {
                int row = g >> 2, c = g & 3;
                cp_async16(dstb + (row * PSROW + c * 8) * 2,
                           g_yb + (size_t)(j0 + row) * HDIM + kt + c * 8);
            } else {
                int gb = g - 512;
                int row = gb >> 2, c = gb & 3;
                cp_async16(dstb + PA_BYTES + (row * PSROW + c * 8) * 2,
                           g_wb + (size_t)(s0 + row) * HDIM + kt + c * 8);
            }
        }
        CP_COMMIT();
    };

    load_chunk(sbase, 0);

    const int sub = lane >> 3, r8 = lane & 7;

    int buf = 0;
    #pragma unroll 1
    for (int it = 0; it < 8; it++) {
        if (it < 7) { load_chunk(sbase + (1 - buf) * PBUF_BYTES, (it + 1) * 32); CP_WAIT1(); }
        else        { CP_WAIT0(); }
        __syncthreads();

        const uint32_t aBase = sbase + buf * PBUF_BYTES;
        const uint32_t bBase = aBase + PA_BYTES;

        #pragma unroll
        for (int kk = 0; kk < 32; kk += 16) {
            uint32_t afrag[4][4];
            #pragma unroll
            for (int mt = 0; mt < 4; mt++) {
                int row = wm0 + mt * 16 + (sub & 1) * 8 + r8;
                int col = kk + (sub >> 1) * 8;
                ldsm_x4(afrag[mt], aBase + (row * PSROW + col) * 2);
            }
            uint32_t bfrag[4][2];
            #pragma unroll
            for (int p = 0; p < 2; p++) {
                int row = wn0 + p * 16 + (sub >> 1) * 8 + r8;
                int col = kk + (sub & 1) * 8;
                uint32_t t4[4];
                ldsm_x4(t4, bBase + (row * PSROW + col) * 2);
                bfrag[p * 2 + 0][0] = t4[0]; bfrag[p * 2 + 0][1] = t4[1];
                bfrag[p * 2 + 1][0] = t4[2]; bfrag[p * 2 + 1][1] = t4[3];
            }
            #pragma unroll
            for (int mt = 0; mt < 4; mt++)
                #pragma unroll
                for (int nt = 0; nt < 4; nt++)
                    mma16816(acc[mt][nt], afrag[mt], bfrag[nt]);
        }
        __syncthreads();
        buf ^= 1;
    }

    #pragma unroll
    for (int nt = 0; nt < 4; nt++) {
        const int gc = s0 + wn0 + nt * 8 + 2 * (lane & 3);
        const float b0 = bias[gc], b1 = bias[gc + 1];
        #pragma unroll
        for (int mt = 0; mt < 4; mt++) {
            const int rlo = j0 + wm0 + mt * 16 + (lane >> 2);
            *((__nv_bfloat162*)&g_projb[(size_t)rlo * HDIM + gc]) =
                __floats2bfloat162_rn(acc[mt][nt][0] + b0, acc[mt][nt][1] + b1);
            *((__nv_bfloat162*)&g_projb[(size_t)(rlo + 8) * HDIM + gc]) =
                __floats2bfloat162_rn(acc[mt][nt][2] + b0, acc[mt][nt][3] + b1);
        }
    }
}

// ===========================================================================
// S2: fused HMMA bf16 GEMM + sigmoid + row partials.
//   CTA 128(M=i) x 128(N=j); 4 warps as 2(M) x 2(N); warp tile 64x64.
//   K=256 as 4 BK=64 chunks in a 3-stage ring; ONE sync per chunk:
//     per chunk g: issue load(g+1) -> wait_group 1 -> __syncthreads -> MMA.
//   (WAR safe: load(g+1) writes stage (g+1)%3, last read at chunk g-2,
//    which every warp finished before the previous iteration's barrier.)
//   Rows padded 128B+16B = 144B stride -> ldmatrix conflict-free.
// ===========================================================================
#define SROWB 144                                   // bytes per smem row
#define STG_A (128 * SROWB)                         // 18432
#define STG_BYTES (2 * STG_A)                       // 36864 (A + B)
#define NST 3
#define SROWS_OFF (NST * STG_BYTES)                 // 110592
#define FUSED_SMEM (SROWS_OFF + 2 * 128 * 4)        // 111616

__global__ void __launch_bounds__(128, 2) fused_hmma_kernel() {
    extern __shared__ __align__(16) char smem[];
    const uint32_t sbase = (uint32_t)__cvta_generic_to_shared(smem);
    float* s_rows = (float*)(smem + SROWS_OFF);     // [2][128]

    const int tid = threadIdx.x;
    const int wid = tid >> 5, lane = tid & 31;
    const int wm0 = (wid & 1) * 64;
    const int wn0 = (wid >> 1) * 64;
    const int sub = lane >> 3, r8 = lane & 7;
    const int i0 = blockIdx.y * 128;
    const int j0 = blockIdx.x * 128;

    float acc[4][8][4];
    #pragma unroll
    for (int mt = 0; mt < 4; mt++)
        #pragma unroll
        for (int nt = 0; nt < 8; nt++)
            #pragma unroll
            for (int e = 0; e < 4; e++) acc[mt][nt][e] = 0.0f;

    // chunk loader: A 1024 + B 1024 granules of 16 B; 16 per thread
    auto load_chunk = [&](int g) {
        const uint32_t dstb = sbase + (g % NST) * STG_BYTES;
        const int kt = g * 64;
        #pragma unroll
        for (int t = 0; t < 16; t++) {
            int gg = tid + t * 128;
            if (gg < 1024) {
                int row = gg >> 3, c = gg & 7;
                cp_async16(dstb + row * SROWB + c * 16,
                           g_ya + (size_t)(i0 + row) * HDIM + kt + c * 8);
            } else {
                int gb = gg - 1024;
                int row = gb >> 3, c = gb & 7;
                cp_async16(dstb + STG_A + row * SROWB + c * 16,
                           g_projb + (size_t)(j0 + row) * HDIM + kt + c * 8);
            }
        }
        CP_COMMIT();
    };

    load_chunk(0);

    #pragma unroll 1
    for (int g = 0; g < 4; g++) {
        if (g < 3) { load_chunk(g + 1); CP_WAIT1(); }
        else       { CP_WAIT0(); }
        __syncthreads();                     // all threads' chunk-g data visible

        const uint32_t aBase = sbase + (g % NST) * STG_BYTES;
        const uint32_t bBase = aBase + STG_A;

        #pragma unroll
        for (int kk = 0; kk < 64; kk += 16) {
            uint32_t afrag[4][4];
            #pragma unroll
            for (int mt = 0; mt < 4; mt++) {
                int row = wm0 + mt * 16 + (sub & 1) * 8 + r8;
                int col = kk + (sub >> 1) * 8;
                ldsm_x4(afrag[mt], aBase + row * SROWB + col * 2);
            }
            uint32_t bfrag[8][2];
            #pragma unroll
            for (int p = 0; p < 4; p++) {
                int row = wn0 + p * 16 + (sub >> 1) * 8 + r8;
                int col = kk + (sub & 1) * 8;
                uint32_t t4[4];
                ldsm_x4(t4, bBase + row * SROWB + col * 2);
                bfrag[p * 2 + 0][0] = t4[0]; bfrag[p * 2 + 0][1] = t4[1];
                bfrag[p * 2 + 1][0] = t4[2]; bfrag[p * 2 + 1][1] = t4[3];
            }
            #pragma unroll
            for (int mt = 0; mt < 4; mt++)
                #pragma unroll
                for (int nt = 0; nt < 8; nt++)
                    mma16816(acc[mt][nt], afrag[mt], bfrag[nt]);
        }
        // no trailing barrier: 3-stage ring makes next iteration's write safe
    }

    // epilogue: sigmoid(x) = 0.5*tanh(x/2) + 0.5
    float rs[4][2];
    #pragma unroll
    for (int mt = 0; mt < 4; mt++) { rs[mt][0] = 0.0f; rs[mt][1] = 0.0f; }
    #pragma unroll
    for (int mt = 0; mt < 4; mt++)
        #pragma unroll
        for (int nt = 0; nt < 8; nt++) {
            rs[mt][0] += 0.5f * fast_tanh(0.5f * acc[mt][nt][0])
                       + 0.5f * fast_tanh(0.5f * acc[mt][nt][1]);
            rs[mt][1] += 0.5f * fast_tanh(0.5f * acc[mt][nt][2])
                       + 0.5f * fast_tanh(0.5f * acc[mt][nt][3]);
        }
    #pragma unroll
    for (int mt = 0; mt < 4; mt++)
        #pragma unroll
        for (int h = 0; h < 2; h++) {
            rs[mt][h] += __shfl_xor_sync(0xffffffffu, rs[mt][h], 1);
            rs[mt][h] += __shfl_xor_sync(0xffffffffu, rs[mt][h], 2);
        }
    __syncthreads();                       // mainloop smem reads done before reuse
    if ((lane & 3) == 0) {
        const int rq = lane >> 2;
        const int wn = wid >> 1;
        #pragma unroll
        for (int mt = 0; mt < 4; mt++) {
            s_rows[wn * 128 + wm0 + mt * 16 + 0 + rq] = rs[mt][0] + 32.0f;
            s_rows[wn * 128 + wm0 + mt * 16 + 8 + rq] = rs[mt][1] + 32.0f;
        }
    }
    __syncthreads();
    g_part[blockIdx.x][i0 + tid] = s_rows[tid] + s_rows[128 + tid];
}

// ===========================================================================
// S3: reduce 64 partials + broadcast. One warp per output row.
// ===========================================================================
__global__ void reduce_bcast_kernel(float* __restrict__ out) {
    const int wid = threadIdx.x >> 5, lane = threadIdx.x & 31;
    const int row = blockIdx.x * 8 + wid;
    float s = g_part[lane][row] + g_part[lane + 32][row];
    #pragma unroll
    for (int d = 16; d > 0; d >>= 1) s += __shfl_xor_sync(0xffffffffu, s, d);
    const float v = s * (1.0f / 256.0f);
    float4* dst = (float4*)(out + (size_t)row * HDIM);
    const float4 vv = make_float4(v, v, v, v);
    dst[lane]      = vv;
    dst[lane + 32] = vv;
}

// ===========================================================================
extern "C" void kernel_launch(void* const* d_in, const int* in_sizes, int n_in,
                              void* d_out, int out_size) {
    const float* y_a = (const float*)d_in[0];
    const float* y_b = (const float*)d_in[1];
    const float* W   = (const float*)d_in[2];
    const float* b   = (const float*)d_in[3];
    float* out = (float*)d_out;

    cudaFuncSetAttribute(fused_hmma_kernel,
                         cudaFuncAttributeMaxDynamicSharedMemorySize, FUSED_SMEM);

    convert_ybw_kernel<<<2112, 256>>>(y_b, W);
    proj_and_convert_kernel<<<256, 256>>>(b, y_a);
    fused_hmma_kernel<<<dim3(NUSR / 128, NUSR / 128), 128, FUSED_SMEM>>>();
    reduce_bcast_kernel<<<NUSR / 8, 256>>>(out);
}

// round 10
// speedup vs baseline: 1.1813x; 1.0173x over previous
#include <cuda_runtime.h>
#include <cuda_fp16.h>
#include <cstdint>

// ---------------------------------------------------------------------------
// miScore: out[i,k] = (1/256) * sum_j sigmoid( y_a[i,:] . (W @ y_b[j,:] + b) )
//
// S0: convert y_b, W fp32 -> fp16
// S1: proj = y_b @ W^T + b (HMMA f16 in / f32 acc, 128 CTAs)
//     || convert y_a -> fp16 (128 CTAs)   -- one launch
// S2: fused HMMA fp16 GEMM with F16 ACCUMULATE + tanh-sigmoid + partials
//     CTA 128x128, 4 warps (64x64 warp tile), BK=32 x 8 chunks, 3-stage ring,
//     one __syncthreads per chunk, 3 CTAs/SM (f16 acc = 64 regs).
// S3: reduce 64 partials + broadcast
// ---------------------------------------------------------------------------

#define NUSR 8192
#define HDIM 256

__device__ __align__(16) __half g_ya[NUSR * HDIM];     // 4 MB
__device__ __align__(16) __half g_yb[NUSR * HDIM];     // 4 MB
__device__ __align__(16) __half g_wb[HDIM * HDIM];     // 128 KB
__device__ __align__(16) __half g_projb[NUSR * HDIM];  // 4 MB
__device__ float g_part[64][NUSR];                     // 2 MB
__device__ float g_s[NUSR];

// ---------------- cp.async helpers ----------------
__device__ __forceinline__ void cp_async16(uint32_t dst, const void* src) {
    asm volatile("cp.async.cg.shared.global [%0], [%1], 16;" :: "r"(dst), "l"(src));
}
#define CP_COMMIT() asm volatile("cp.async.commit_group;" ::: "memory")
#define CP_WAIT1()  asm volatile("cp.async.wait_group 1;" ::: "memory")
#define CP_WAIT0()  asm volatile("cp.async.wait_group 0;" ::: "memory")

// ---------------- mma / ldmatrix ----------------
__device__ __forceinline__ void ldsm_x4(uint32_t* r, uint32_t addr) {
    asm volatile("ldmatrix.sync.aligned.m8n8.x4.shared.b16 {%0,%1,%2,%3}, [%4];"
                 : "=r"(r[0]), "=r"(r[1]), "=r"(r[2]), "=r"(r[3]) : "r"(addr));
}
// f16 inputs, f32 accumulate (proj)
__device__ __forceinline__ void mma16816_f32(float* c, const uint32_t* a, const uint32_t* b) {
    asm volatile(
        "mma.sync.aligned.m16n8k16.row.col.f32.f16.f16.f32 "
        "{%0,%1,%2,%3}, {%4,%5,%6,%7}, {%8,%9}, {%0,%1,%2,%3};"
        : "+f"(c[0]), "+f"(c[1]), "+f"(c[2]), "+f"(c[3])
        : "r"(a[0]), "r"(a[1]), "r"(a[2]), "r"(a[3]), "r"(b[0]), "r"(b[1]));
}
// f16 inputs, F16 accumulate (fused scores GEMM) -- 2 C regs
__device__ __forceinline__ void mma16816_f16(uint32_t* c, const uint32_t* a, const uint32_t* b) {
    asm volatile(
        "mma.sync.aligned.m16n8k16.row.col.f16.f16.f16.f16 "
        "{%0,%1}, {%2,%3,%4,%5}, {%6,%7}, {%0,%1};"
        : "+r"(c[0]), "+r"(c[1])
        : "r"(a[0]), "r"(a[1]), "r"(a[2]), "r"(a[3]), "r"(b[0]), "r"(b[1]));
}
__device__ __forceinline__ float fast_tanh(float x) {
    float t;
    asm("tanh.approx.f32 %0, %1;" : "=f"(t) : "f"(x));
    return t;
}

// ===========================================================================
// S0: convert y_b, W -> fp16. 540672 float4 -> 2112 blocks x 256.
// ===========================================================================
__global__ void convert_ybw_kernel(const float* __restrict__ yb,
                                   const float* __restrict__ W) {
    const int idx = blockIdx.x * 256 + threadIdx.x;
    const float* src;
    __half2* dst;
    int off;
    if (idx < 524288) { src = yb; dst = (__half2*)g_yb; off = idx; }
    else              { src = W;  dst = (__half2*)g_wb; off = idx - 524288; }
    float4 v = ((const float4*)src)[off];
    dst[off * 2 + 0] = __floats2half2_rn(v.x, v.y);
    dst[off * 2 + 1] = __floats2half2_rn(v.z, v.w);
}

// ===========================================================================
// S1: blocks 0..127: proj = y_b @ W^T + b (HMMA f16/f32, CTA 128x128)
//     blocks 128..255: convert y_a -> fp16
// ===========================================================================
#define PSROW 40
#define PA_BYTES (128 * PSROW * 2)
#define PBUF_BYTES (2 * PA_BYTES)

__global__ void __launch_bounds__(256, 1) proj_and_convert_kernel(
        const float* __restrict__ bias, const float* __restrict__ ya) {
    __shared__ __align__(16) char smem[2 * PBUF_BYTES];

    const int tid = threadIdx.x;
    const int bx = blockIdx.x;

    if (bx >= 128) {   // ---- y_a conversion ----
        const int base = (bx - 128) * 4096;
        __half2* dst = (__half2*)g_ya;
        #pragma unroll
        for (int u = 0; u < 16; u++) {
            const int off = base + u * 256 + tid;
            float4 v = ((const float4*)ya)[off];
            dst[off * 2 + 0] = __floats2half2_rn(v.x, v.y);
            dst[off * 2 + 1] = __floats2half2_rn(v.z, v.w);
        }
        return;
    }

    // ---- proj ----
    const uint32_t sbase = (uint32_t)__cvta_generic_to_shared(smem);
    const int wid = tid >> 5, lane = tid & 31;
    const int wm0 = (wid & 1) * 64;
    const int wn0 = (wid >> 1) * 32;
    const int j0 = (bx >> 1) * 128;
    const int s0 = (bx & 1) * 128;

    float acc[4][4][4];
    #pragma unroll
    for (int mt = 0; mt < 4; mt++)
        #pragma unroll
        for (int nt = 0; nt < 4; nt++)
            #pragma unroll
            for (int e = 0; e < 4; e++) acc[mt][nt][e] = 0.0f;

    auto load_chunk = [&](uint32_t dstb, int kt) {
        #pragma unroll
        for (int t = 0; t < 4; t++) {
            int g = tid + t * 256;
            if (g < 512) {
                int row = g >> 2, c = g & 3;
                cp_async16(dstb + (row * PSROW + c * 8) * 2,
                           g_yb + (size_t)(j0 + row) * HDIM + kt + c * 8);
            } else {
                int gb = g - 512;
                int row = gb >> 2, c = gb & 3;
                cp_async16(dstb + PA_BYTES + (row * PSROW + c * 8) * 2,
                           g_wb + (size_t)(s0 + row) * HDIM + kt + c * 8);
            }
        }
        CP_COMMIT();
    };

    load_chunk(sbase, 0);

    const int sub = lane >> 3, r8 = lane & 7;

    int buf = 0;
    #pragma unroll 1
    for (int it = 0; it < 8; it++) {
        if (it < 7) { load_chunk(sbase + (1 - buf) * PBUF_BYTES, (it + 1) * 32); CP_WAIT1(); }
        else        { CP_WAIT0(); }
        __syncthreads();

        const uint32_t aBase = sbase + buf * PBUF_BYTES;
        const uint32_t bBase = aBase + PA_BYTES;

        #pragma unroll
        for (int kk = 0; kk < 32; kk += 16) {
            uint32_t afrag[4][4];
            #pragma unroll
            for (int mt = 0; mt < 4; mt++) {
                int row = wm0 + mt * 16 + (sub & 1) * 8 + r8;
                int col = kk + (sub >> 1) * 8;
                ldsm_x4(afrag[mt], aBase + (row * PSROW + col) * 2);
            }
            uint32_t bfrag[4][2];
            #pragma unroll
            for (int p = 0; p < 2; p++) {
                int row = wn0 + p * 16 + (sub >> 1) * 8 + r8;
                int col = kk + (sub & 1) * 8;
                uint32_t t4[4];
                ldsm_x4(t4, bBase + (row * PSROW + col) * 2);
                bfrag[p * 2 + 0][0] = t4[0]; bfrag[p * 2 + 0][1] = t4[1];
                bfrag[p * 2 + 1][0] = t4[2]; bfrag[p * 2 + 1][1] = t4[3];
            }
            #pragma unroll
            for (int mt = 0; mt < 4; mt++)
                #pragma unroll
                for (int nt = 0; nt < 4; nt++)
                    mma16816_f32(acc[mt][nt], afrag[mt], bfrag[nt]);
        }
        __syncthreads();
        buf ^= 1;
    }

    #pragma unroll
    for (int nt = 0; nt < 4; nt++) {
        const int gc = s0 + wn0 + nt * 8 + 2 * (lane & 3);
        const float b0 = bias[gc], b1 = bias[gc + 1];
        #pragma unroll
        for (int mt = 0; mt < 4; mt++) {
            const int rlo = j0 + wm0 + mt * 16 + (lane >> 2);
            *((__half2*)&g_projb[(size_t)rlo * HDIM + gc]) =
                __floats2half2_rn(acc[mt][nt][0] + b0, acc[mt][nt][1] + b1);
            *((__half2*)&g_projb[(size_t)(rlo + 8) * HDIM + gc]) =
                __floats2half2_rn(acc[mt][nt][2] + b0, acc[mt][nt][3] + b1);
        }
    }
}

// ===========================================================================
// S2: fused HMMA fp16 GEMM (f16 accumulate) + sigmoid + row partials.
//   CTA 128x128; 4 warps 2(M)x2(N); warp tile 64x64; f16 acc = 64 regs.
//   K=256 as 8 BK=32 chunks, 3-stage ring, one sync per chunk. 3 CTAs/SM.
//   SMEM rows: 32 f16 = 64 B + 16 B pad = 80 B stride (conflict-free ldsm).
// ===========================================================================
#define SROWB 80
#define STG_A (128 * SROWB)                         // 10240
#define STG_BYTES (2 * STG_A)                       // 20480 (A + B)
#define NST 3
#define SROWS_OFF (NST * STG_BYTES)                 // 61440
#define FUSED_SMEM (SROWS_OFF + 2 * 128 * 4)        // 62464

__global__ void __launch_bounds__(128, 3) fused_hmma_kernel() {
    extern __shared__ __align__(16) char smem[];
    const uint32_t sbase = (uint32_t)__cvta_generic_to_shared(smem);
    float* s_rows = (float*)(smem + SROWS_OFF);     // [2][128]

    const int tid = threadIdx.x;
    const int wid = tid >> 5, lane = tid & 31;
    const int wm0 = (wid & 1) * 64;
    const int wn0 = (wid >> 1) * 64;
    const int sub = lane >> 3, r8 = lane & 7;
    const int i0 = blockIdx.y * 128;
    const int j0 = blockIdx.x * 128;

    uint32_t acc[4][8][2];
    #pragma unroll
    for (int mt = 0; mt < 4; mt++)
        #pragma unroll
        for (int nt = 0; nt < 8; nt++) { acc[mt][nt][0] = 0u; acc[mt][nt][1] = 0u; }

    // chunk loader: A 512 + B 512 granules of 16 B; 8 per thread
    auto load_chunk = [&](int g) {
        const uint32_t dstb = sbase + (g % NST) * STG_BYTES;
        const int kt = g * 32;
        #pragma unroll
        for (int t = 0; t < 8; t++) {
            int gg = tid + t * 128;
            if (gg < 512) {
                int row = gg >> 2, c = gg & 3;
                cp_async16(dstb + row * SROWB + c * 16,
                           g_ya + (size_t)(i0 + row) * HDIM + kt + c * 8);
            } else {
                int gb = gg - 512;
                int row = gb >> 2, c = gb & 3;
                cp_async16(dstb + STG_A + row * SROWB + c * 16,
                           g_projb + (size_t)(j0 + row) * HDIM + kt + c * 8);
            }
        }
        CP_COMMIT();
    };

    load_chunk(0);
    load_chunk(1);

    #pragma unroll 1
    for (int g = 0; g < 8; g++) {
        if (g < 6)      { load_chunk(g + 2); CP_WAIT1(); }   // keep depth 2
        else if (g == 6){ CP_WAIT1(); }
        else            { CP_WAIT0(); }
        __syncthreads();       // chunk g visible; ring stage g+2 safe (3-stage)

        const uint32_t aBase = sbase + (g % NST) * STG_BYTES;
        const uint32_t bBase = aBase + STG_A;

        #pragma unroll
        for (int kk = 0; kk < 32; kk += 16) {
            uint32_t afrag[4][4];
            #pragma unroll
            for (int mt = 0; mt < 4; mt++) {
                int row = wm0 + mt * 16 + (sub & 1) * 8 + r8;
                int col = kk + (sub >> 1) * 8;
                ldsm_x4(afrag[mt], aBase + row * SROWB + col * 2);
            }
            uint32_t bfrag[8][2];
            #pragma unroll
            for (int p = 0; p < 4; p++) {
                int row = wn0 + p * 16 + (sub >> 1) * 8 + r8;
                int col = kk + (sub & 1) * 8;
                uint32_t t4[4];
                ldsm_x4(t4, bBase + row * SROWB + col * 2);
                bfrag[p * 2 + 0][0] = t4[0]; bfrag[p * 2 + 0][1] = t4[1];
                bfrag[p * 2 + 1][0] = t4[2]; bfrag[p * 2 + 1][1] = t4[3];
            }
            #pragma unroll
            for (int mt = 0; mt < 4; mt++)
                #pragma unroll
                for (int nt = 0; nt < 8; nt++)
                    mma16816_f16(acc[mt][nt], afrag[mt], bfrag[nt]);
        }
        // no trailing barrier (3-stage ring; next write targets stage read 2 ago)
    }

    // epilogue: sigmoid(x) = 0.5*tanh(x/2) + 0.5
    // c[0] = row (wm0+mt*16+lane/4),   2 cols as f16x2
    // c[1] = row (wm0+mt*16+8+lane/4), 2 cols as f16x2
    float rs[4][2];
    #pragma unroll
    for (int mt = 0; mt < 4; mt++) { rs[mt][0] = 0.0f; rs[mt][1] = 0.0f; }
    #pragma unroll
    for (int mt = 0; mt < 4; mt++)
        #pragma unroll
        for (int nt = 0; nt < 8; nt++) {
            float2 v0 = __half22float2(*(__half2*)&acc[mt][nt][0]);
            float2 v1 = __half22float2(*(__half2*)&acc[mt][nt][1]);
            rs[mt][0] += 0.5f * fast_tanh(0.5f * v0.x) + 0.5f * fast_tanh(0.5f * v0.y);
            rs[mt][1] += 0.5f * fast_tanh(0.5f * v1.x) + 0.5f * fast_tanh(0.5f * v1.y);
        }
    #pragma unroll
    for (int mt = 0; mt < 4; mt++)
        #pragma unroll
        for (int h = 0; h < 2; h++) {
            rs[mt][h] += __shfl_xor_sync(0xffffffffu, rs[mt][h], 1);
            rs[mt][h] += __shfl_xor_sync(0xffffffffu, rs[mt][h], 2);
        }
    __syncthreads();              // mainloop smem reads done before s_rows reuse
    if ((lane & 3) == 0) {
        const int rq = lane >> 2;
        const int wn = wid >> 1;
        #pragma unroll
        for (int mt = 0; mt < 4; mt++) {
            s_rows[wn * 128 + wm0 + mt * 16 + 0 + rq] = rs[mt][0] + 32.0f;
            s_rows[wn * 128 + wm0 + mt * 16 + 8 + rq] = rs[mt][1] + 32.0f;
        }
    }
    __syncthreads();
    g_part[blockIdx.x][i0 + tid] = s_rows[tid] + s_rows[128 + tid];
}

// ===========================================================================
// S3: reduce 64 partials + broadcast. One warp per output row.
// ===========================================================================
__global__ void reduce_bcast_kernel(float* __restrict__ out) {
    const int wid = threadIdx.x >> 5, lane = threadIdx.x & 31;
    const int row = blockIdx.x * 8 + wid;
    float s = g_part[lane][row] + g_part[lane + 32][row];
    #pragma unroll
    for (int d = 16; d > 0; d >>= 1) s += __shfl_xor_sync(0xffffffffu, s, d);
    const float v = s * (1.0f / 256.0f);
    float4* dst = (float4*)(out + (size_t)row * HDIM);
    const float4 vv = make_float4(v, v, v, v);
    dst[lane]      = vv;
    dst[lane + 32] = vv;
}

// ===========================================================================
extern "C" void kernel_launch(void* const* d_in, const int* in_sizes, int n_in,
                              void* d_out, int out_size) {
    const float* y_a = (const float*)d_in[0];
    const float* y_b = (const float*)d_in[1];
    const float* W   = (const float*)d_in[2];
    const float* b   = (const float*)d_in[3];
    float* out = (float*)d_out;

    cudaFuncSetAttribute(fused_hmma_kernel,
                         cudaFuncAttributeMaxDynamicSharedMemorySize, FUSED_SMEM);

    convert_ybw_kernel<<<2112, 256>>>(y_b, W);
    proj_and_convert_kernel<<<256, 256>>>(b, y_a);
    fused_hmma_kernel<<<dim3(NUSR / 128, NUSR / 128), 128, FUSED_SMEM>>>();
    reduce_bcast_kernel<<<NUSR / 8, 256>>>(out);
}

// round 11
// speedup vs baseline: 1.1830x; 1.0014x over previous
#include <cuda_runtime.h>
#include <cuda_bf16.h>
#include <cstdint>

// ---------------------------------------------------------------------------
// miScore: out[i,k] = (1/256) * sum_j sigmoid( y_a[i,:] . (W @ y_b[j,:] + b) )
//
// S0: convert y_b, W fp32 -> bf16 ; zero g_s (spare blocks)
// S1: proj = y_b @ W^T + b (HMMA bf16/f32, 128 CTAs) || convert y_a (128 CTAs)
// S2: fused HMMA bf16 GEMM (f32 acc) + tanh-sigmoid + atomicAdd row sums
//     CTA 128x128, 4 warps (64x64 warp tile), BK=64 x 4 chunks, 3-stage ring,
//     one __syncthreads per chunk, 2 CTAs/SM.
// S3: broadcast g_s/256 to out
// ---------------------------------------------------------------------------

#define NUSR 8192
#define HDIM 256

__device__ __align__(16) __nv_bfloat16 g_ya[NUSR * HDIM];     // 4 MB
__device__ __align__(16) __nv_bfloat16 g_yb[NUSR * HDIM];     // 4 MB
__device__ __align__(16) __nv_bfloat16 g_wb[HDIM * HDIM];     // 128 KB
__device__ __align__(16) __nv_bfloat16 g_projb[NUSR * HDIM];  // 4 MB
__device__ float g_s[NUSR];

// ---------------- cp.async helpers ----------------
__device__ __forceinline__ void cp_async16(uint32_t dst, const void* src) {
    asm volatile("cp.async.cg.shared.global [%0], [%1], 16;" :: "r"(dst), "l"(src));
}
#define CP_COMMIT() asm volatile("cp.async.commit_group;" ::: "memory")
#define CP_WAIT1()  asm volatile("cp.async.wait_group 1;" ::: "memory")
#define CP_WAIT0()  asm volatile("cp.async.wait_group 0;" ::: "memory")

// ---------------- mma / ldmatrix ----------------
__device__ __forceinline__ void ldsm_x4(uint32_t* r, uint32_t addr) {
    asm volatile("ldmatrix.sync.aligned.m8n8.x4.shared.b16 {%0,%1,%2,%3}, [%4];"
                 : "=r"(r[0]), "=r"(r[1]), "=r"(r[2]), "=r"(r[3]) : "r"(addr));
}
__device__ __forceinline__ void mma16816(float* c, const uint32_t* a, const uint32_t* b) {
    asm volatile(
        "mma.sync.aligned.m16n8k16.row.col.f32.bf16.bf16.f32 "
        "{%0,%1,%2,%3}, {%4,%5,%6,%7}, {%8,%9}, {%0,%1,%2,%3};"
        : "+f"(c[0]), "+f"(c[1]), "+f"(c[2]), "+f"(c[3])
        : "r"(a[0]), "r"(a[1]), "r"(a[2]), "r"(a[3]), "r"(b[0]), "r"(b[1]));
}
__device__ __forceinline__ float fast_tanh(float x) {
    float t;
    asm("tanh.approx.f32 %0, %1;" : "=f"(t) : "f"(x));
    return t;
}

// ===========================================================================
// S0: convert y_b, W -> bf16 (blocks 0..2111); zero g_s (blocks 2112..2119).
// ===========================================================================
__global__ void convert_ybw_kernel(const float* __restrict__ yb,
                                   const float* __restrict__ W) {
    const int bx = blockIdx.x;
    if (bx >= 2112) {     // zero g_s: 8 blocks x 256 thr x 4 floats
        const int o = (bx - 2112) * 1024 + threadIdx.x * 4;
        *(float4*)&g_s[o] = make_float4(0.f, 0.f, 0.f, 0.f);
        return;
    }
    const int idx = bx * 256 + threadIdx.x;
    const float* src;
    __nv_bfloat162* dst;
    int off;
    if (idx < 524288) { src = yb; dst = (__nv_bfloat162*)g_yb; off = idx; }
    else              { src = W;  dst = (__nv_bfloat162*)g_wb; off = idx - 524288; }
    float4 v = ((const float4*)src)[off];
    dst[off * 2 + 0] = __floats2bfloat162_rn(v.x, v.y);
    dst[off * 2 + 1] = __floats2bfloat162_rn(v.z, v.w);
}

// ===========================================================================
// S1: blocks 0..127: proj = y_b @ W^T + b (HMMA, CTA 128x128)
//     blocks 128..255: convert y_a -> bf16
// ===========================================================================
#define PSROW 40
#define PA_BYTES (128 * PSROW * 2)
#define PBUF_BYTES (2 * PA_BYTES)

__global__ void __launch_bounds__(256, 1) proj_and_convert_kernel(
        const float* __restrict__ bias, const float* __restrict__ ya) {
    __shared__ __align__(16) char smem[2 * PBUF_BYTES];

    const int tid = threadIdx.x;
    const int bx = blockIdx.x;

    if (bx >= 128) {   // ---- y_a conversion blocks ----
        const int base = (bx - 128) * 4096;
        __nv_bfloat162* dst = (__nv_bfloat162*)g_ya;
        #pragma unroll
        for (int u = 0; u < 16; u++) {
            const int off = base + u * 256 + tid;
            float4 v = ((const float4*)ya)[off];
            dst[off * 2 + 0] = __floats2bfloat162_rn(v.x, v.y);
            dst[off * 2 + 1] = __floats2bfloat162_rn(v.z, v.w);
        }
        return;
    }

    // ---- proj blocks ----
    const uint32_t sbase = (uint32_t)__cvta_generic_to_shared(smem);
    const int wid = tid >> 5, lane = tid & 31;
    const int wm0 = (wid & 1) * 64;
    const int wn0 = (wid >> 1) * 32;
    const int j0 = (bx >> 1) * 128;
    const int s0 = (bx & 1) * 128;

    float acc[4][4][4];
    #pragma unroll
    for (int mt = 0; mt < 4; mt++)
        #pragma unroll
        for (int nt = 0; nt < 4; nt++)
            #pragma unroll
            for (int e = 0; e < 4; e++) acc[mt][nt][e] = 0.0f;

    auto load_chunk = [&](uint32_t dstb, int kt) {
        #pragma unroll
        for (int t = 0; t < 4; t++) {
            int g = tid + t * 256;
            if (g < 512) {
                int row = g >> 2, c = g & 3;
                cp_async16(dstb + (row * PSROW + c * 8) * 2,
                           g_yb + (size_t)(j0 + row) * HDIM + kt + c * 8);
            } else {
                int gb = g - 512;
                int row = gb >> 2, c = gb & 3;
                cp_async16(dstb + PA_BYTES + (row * PSROW + c * 8) * 2,
                           g_wb + (size_t)(s0 + row) * HDIM + kt + c * 8);
            }
        }
        CP_COMMIT();
    };

    load_chunk(sbase, 0);

    const int sub = lane >> 3, r8 = lane & 7;

    int buf = 0;
    #pragma unroll 1
    for (int it = 0; it < 8; it++) {
        if (it < 7) { load_chunk(sbase + (1 - buf) * PBUF_BYTES, (it + 1) * 32); CP_WAIT1(); }
        else        { CP_WAIT0(); }
        __syncthreads();

        const uint32_t aBase = sbase + buf * PBUF_BYTES;
        const uint32_t bBase = aBase + PA_BYTES;

        #pragma unroll
        for (int kk = 0; kk < 32; kk += 16) {
            uint32_t afrag[4][4];
            #pragma unroll
            for (int mt = 0; mt < 4; mt++) {
                int row = wm0 + mt * 16 + (sub & 1) * 8 + r8;
                int col = kk + (sub >> 1) * 8;
                ldsm_x4(afrag[mt], aBase + (row * PSROW + col) * 2);
            }
            uint32_t bfrag[4][2];
            #pragma unroll
            for (int p = 0; p < 2; p++) {
                int row = wn0 + p * 16 + (sub >> 1) * 8 + r8;
                int col = kk + (sub & 1) * 8;
                uint32_t t4[4];
                ldsm_x4(t4, bBase + (row * PSROW + col) * 2);
                bfrag[p * 2 + 0][0] = t4[0]; bfrag[p * 2 + 0][1] = t4[1];
                bfrag[p * 2 + 1][0] = t4[2]; bfrag[p * 2 + 1][1] = t4[3];
            }
            #pragma unroll
            for (int mt = 0; mt < 4; mt++)
                #pragma unroll
                for (int nt = 0; nt < 4; nt++)
                    mma16816(acc[mt][nt], afrag[mt], bfrag[nt]);
        }
        __syncthreads();
        buf ^= 1;
    }

    #pragma unroll
    for (int nt = 0; nt < 4; nt++) {
        const int gc = s0 + wn0 + nt * 8 + 2 * (lane & 3);
        const float b0 = bias[gc], b1 = bias[gc + 1];
        #pragma unroll
        for (int mt = 0; mt < 4; mt++) {
            const int rlo = j0 + wm0 + mt * 16 + (lane >> 2);
            *((__nv_bfloat162*)&g_projb[(size_t)rlo * HDIM + gc]) =
                __floats2bfloat162_rn(acc[mt][nt][0] + b0, acc[mt][nt][1] + b1);
            *((__nv_bfloat162*)&g_projb[(size_t)(rlo + 8) * HDIM + gc]) =
                __floats2bfloat162_rn(acc[mt][nt][2] + b0, acc[mt][nt][3] + b1);
        }
    }
}

// ===========================================================================
// S2: fused HMMA bf16 GEMM (f32 acc) + sigmoid + atomic row sums.
//   CTA 128(M=i) x 128(N=j); 4 warps 2(M) x 2(N); warp tile 64x64.
//   K=256 as 4 BK=64 chunks, 3-stage ring, ONE sync per chunk. 2 CTAs/SM.
//   Epilogue: tanh-sigmoid, quad shfl reduce, atomicAdd into g_s.
// ===========================================================================
#define SROWB 144                                   // bytes per smem row
#define STG_A (128 * SROWB)                         // 18432
#define STG_BYTES (2 * STG_A)                       // 36864 (A + B)
#define NST 3
#define FUSED_SMEM (NST * STG_BYTES)                // 110592

__global__ void __launch_bounds__(128, 2) fused_hmma_kernel() {
    extern __shared__ __align__(16) char smem[];
    const uint32_t sbase = (uint32_t)__cvta_generic_to_shared(smem);

    const int tid = threadIdx.x;
    const int wid = tid >> 5, lane = tid & 31;
    const int wm0 = (wid & 1) * 64;
    const int wn0 = (wid >> 1) * 64;
    const int sub = lane >> 3, r8 = lane & 7;
    const int i0 = blockIdx.y * 128;
    const int j0 = blockIdx.x * 128;

    float acc[4][8][4];
    #pragma unroll
    for (int mt = 0; mt < 4; mt++)
        #pragma unroll
        for (int nt = 0; nt < 8; nt++)
            #pragma unroll
            for (int e = 0; e < 4; e++) acc[mt][nt][e] = 0.0f;

    auto load_chunk = [&](int g) {
        const uint32_t dstb = sbase + (g % NST) * STG_BYTES;
        const int kt = g * 64;
        #pragma unroll
        for (int t = 0; t < 16; t++) {
            int gg = tid + t * 128;
            if (gg < 1024) {
                int row = gg >> 3, c = gg & 7;
                cp_async16(dstb + row * SROWB + c * 16,
                           g_ya + (size_t)(i0 + row) * HDIM + kt + c * 8);
            } else {
                int gb = gg - 1024;
                int row = gb >> 3, c = gb & 7;
                cp_async16(dstb + STG_A + row * SROWB + c * 16,
                           g_projb + (size_t)(j0 + row) * HDIM + kt + c * 8);
            }
        }
        CP_COMMIT();
    };

    load_chunk(0);

    #pragma unroll 1
    for (int g = 0; g < 4; g++) {
        if (g < 3) { load_chunk(g + 1); CP_WAIT1(); }
        else       { CP_WAIT0(); }
        __syncthreads();

        const uint32_t aBase = sbase + (g % NST) * STG_BYTES;
        const uint32_t bBase = aBase + STG_A;

        #pragma unroll
        for (int kk = 0; kk < 64; kk += 16) {
            uint32_t afrag[4][4];
            #pragma unroll
            for (int mt = 0; mt < 4; mt++) {
                int row = wm0 + mt * 16 + (sub & 1) * 8 + r8;
                int col = kk + (sub >> 1) * 8;
                ldsm_x4(afrag[mt], aBase + row * SROWB + col * 2);
            }
            uint32_t bfrag[8][2];
            #pragma unroll
            for (int p = 0; p < 4; p++) {
                int row = wn0 + p * 16 + (sub >> 1) * 8 + r8;
                int col = kk + (sub & 1) * 8;
                uint32_t t4[4];
                ldsm_x4(t4, bBase + row * SROWB + col * 2);
                bfrag[p * 2 + 0][0] = t4[0]; bfrag[p * 2 + 0][1] = t4[1];
                bfrag[p * 2 + 1][0] = t4[2]; bfrag[p * 2 + 1][1] = t4[3];
            }
            #pragma unroll
            for (int mt = 0; mt < 4; mt++)
                #pragma unroll
                for (int nt = 0; nt < 8; nt++)
                    mma16816(acc[mt][nt], afrag[mt], bfrag[nt]);
        }
        // no trailing barrier: 3-stage ring makes next iteration's write safe
    }

    // ---- epilogue: sigmoid(x) = 0.5*tanh(x/2) + 0.5 ; atomic row sums ----
    float rs[4][2];
    #pragma unroll
    for (int mt = 0; mt < 4; mt++) { rs[mt][0] = 0.0f; rs[mt][1] = 0.0f; }
    #pragma unroll
    for (int mt = 0; mt < 4; mt++)
        #pragma unroll
        for (int nt = 0; nt < 8; nt++) {
            rs[mt][0] += 0.5f * fast_tanh(0.5f * acc[mt][nt][0])
                       + 0.5f * fast_tanh(0.5f * acc[mt][nt][1]);
            rs[mt][1] += 0.5f * fast_tanh(0.5f * acc[mt][nt][2])
                       + 0.5f * fast_tanh(0.5f * acc[mt][nt][3]);
        }
    #pragma unroll
    for (int mt = 0; mt < 4; mt++)
        #pragma unroll
        for (int h = 0; h < 2; h++) {
            rs[mt][h] += __shfl_xor_sync(0xffffffffu, rs[mt][h], 1);
            rs[mt][h] += __shfl_xor_sync(0xffffffffu, rs[mt][h], 2);
        }
    if ((lane & 3) == 0) {
        const int rq = lane >> 2;                 // 0..7
        // each rs bucket covers 64 columns -> add 64 * 0.5 = 32 constant
        #pragma unroll
        for (int mt = 0; mt < 4; mt++) {
            atomicAdd(&g_s[i0 + wm0 + mt * 16 + 0 + rq], rs[mt][0] + 32.0f);
            atomicAdd(&g_s[i0 + wm0 + mt * 16 + 8 + rq], rs[mt][1] + 32.0f);
        }
    }
}

// ===========================================================================
// S3: broadcast g_s/256 to out. One warp per output row.
// ===========================================================================
__global__ void bcast_kernel(float* __restrict__ out) {
    const int wid = threadIdx.x >> 5, lane = threadIdx.x & 31;
    const int row = blockIdx.x * 8 + wid;
    const float v = g_s[row] * (1.0f / 256.0f);
    float4* dst = (float4*)(out + (size_t)row * HDIM);
    const float4 vv = make_float4(v, v, v, v);
    dst[lane]      = vv;
    dst[lane + 32] = vv;
}

// ===========================================================================
extern "C" void kernel_launch(void* const* d_in, const int* in_sizes, int n_in,
                              void* d_out, int out_size) {
    const float* y_a = (const float*)d_in[0];
    const float* y_b = (const float*)d_in[1];
    const float* W   = (const float*)d_in[2];
    const float* b   = (const float*)d_in[3];
    float* out = (float*)d_out;

    cudaFuncSetAttribute(fused_hmma_kernel,
                         cudaFuncAttributeMaxDynamicSharedMemorySize, FUSED_SMEM);

    convert_ybw_kernel<<<2120, 256>>>(y_b, W);
    proj_and_convert_kernel<<<256, 256>>>(b, y_a);
    fused_hmma_kernel<<<dim3(NUSR / 128, NUSR / 128), 128, FUSED_SMEM>>>();
    bcast_kernel<<<NUSR / 8, 256>>>(out);
}